// round 16
// baseline (speedup 1.0000x reference)
#include <cuda_runtime.h>

#define NELEM 16384
#define NB 8192                       // buckets per array (power of two)
#define NBW (NB / 32)                 // bitmask words per array (256)
#define CAP 16                        // slots per bucket (lambda=2 -> P(>16) ~ 1e-10)
#define NBLK 64
#define NTHR 512
#define RANGE_LO (-6.0f)
#define RANGE_HI (6.0f)
#define INV_BW ((float)NB / (RANGE_HI - RANGE_LO))

// Scratch (device globals; no allocations). Zero-initialized at load; the
// search kernel's last-done block re-zeroes all mutable state, and the next
// graph replay's build kernel starts only after the search kernel completes,
// so every replay sees identical initial state.
// Slots beyond a bucket's final count are NEVER written in any replay (same
// input -> same counts), so unconditional slot reads see zero-init data that
// the idx<cnt mask discards.
__device__ int      g_cnt[2][NB];        // per-bucket counts (atomic rank source)
__device__ unsigned g_bits[2][NBW];      // non-empty bucket bitmask
__device__ float    g_slot[2][NB][CAP];  // bucket slots (64B-aligned per bucket)
__device__ int      g_ovf_cnt[2];        // overflow counts (normally 0)
__device__ float    g_ovf[2][NELEM];     // overflow values (worst-case capacity)
__device__ float    g_partials[NBLK];
__device__ int      g_done;              // completion counter (search kernel)

__device__ __forceinline__ int bucket_of(float v) {
    int b = (int)((v - RANGE_LO) * INV_BW);
    return min(max(b, 0), NB - 1);       // clamp outliers into end buckets
}

// Vectorized bucket scan (slots 0..7 unconditional; 8..15 only if c>8).
__device__ __forceinline__ float scan_bucket(int sa, int bkt, float v, float best) {
    const int c = min(g_cnt[sa][bkt], CAP);
    const float4* sv = reinterpret_cast<const float4*>(g_slot[sa][bkt]);
#pragma unroll
    for (int k = 0; k < 2; k++) {
        const float4 s = sv[k];
        const int i0 = k * 4;
        if (i0 + 0 < c) best = fminf(best, fabsf(s.x - v));
        if (i0 + 1 < c) best = fminf(best, fabsf(s.y - v));
        if (i0 + 2 < c) best = fminf(best, fabsf(s.z - v));
        if (i0 + 3 < c) best = fminf(best, fabsf(s.w - v));
    }
    if (c > 8) {
#pragma unroll
        for (int k = 2; k < 4; k++) {
            const float4 s = sv[k];
            const int i0 = k * 4;
            if (i0 + 0 < c) best = fminf(best, fabsf(s.x - v));
            if (i0 + 1 < c) best = fminf(best, fabsf(s.y - v));
            if (i0 + 2 < c) best = fminf(best, fabsf(s.z - v));
            if (i0 + 3 < c) best = fminf(best, fabsf(s.w - v));
        }
    }
    return best;
}

// Own-bucket scan that also reports whether a value <= v / >= v was seen.
__device__ __forceinline__ float scan_bucket_flags(int sa, int bkt, float v,
                                                   float best,
                                                   bool* hasLow, bool* hasHigh) {
    const int c = min(g_cnt[sa][bkt], CAP);
    const float4* sv = reinterpret_cast<const float4*>(g_slot[sa][bkt]);
    bool hl = false, hh = false;
#pragma unroll
    for (int k = 0; k < 4; k++) {
        if (k == 2 && c <= 8) break;
        const float4 s = sv[k];
        const float e[4] = {s.x, s.y, s.z, s.w};
#pragma unroll
        for (int j = 0; j < 4; j++) {
            if (k * 4 + j < c) {
                const float sj = e[j];
                best = fminf(best, fabsf(sj - v));
                hl |= (sj <= v);
                hh |= (sj >= v);
            }
        }
    }
    *hasLow = hl; *hasHigh = hh;
    return best;
}

// highest set bit index < b, or -1 (smem bitmask)
__device__ __forceinline__ int prev_ne(const unsigned* bits, int b) {
    int w = b >> 5;
    unsigned m = bits[w] & ((1u << (b & 31)) - 1u);
    while (true) {
        if (m) return (w << 5) + 31 - __clz(m);
        if (--w < 0) return -1;
        m = bits[w];
    }
}
// lowest set bit index > b, or -1 (smem bitmask)
__device__ __forceinline__ int next_ne(const unsigned* bits, int b) {
    int w = b >> 5;
    const int r = b & 31;
    unsigned m = bits[w] & ((r == 31) ? 0u : (0xFFFFFFFFu << (r + 1)));
    while (true) {
        if (m) return (w << 5) + __ffs(m) - 1;
        if (++w >= NBW) return -1;
        m = bits[w];
    }
}

// ---------------------------------------------------------------------------
// Kernel 1: build — fused histogram + scatter + bitmask. The graph edge to
// the search kernel is the synchronization (no in-kernel barrier).
// ---------------------------------------------------------------------------
__global__ void __launch_bounds__(NTHR, 1)
build_kernel(const float* __restrict__ x, const float* __restrict__ y) {
    const int gid = blockIdx.x * NTHR + threadIdx.x;   // 0..32767
    const int a   = (gid >= NELEM);
    const int idx = a ? (gid - NELEM) : gid;
    const float v = a ? __ldg(&y[idx]) : __ldg(&x[idx]);
    const int  b  = bucket_of(v);

    // atomicOr first (no return needed): overlaps the atomicAdd round-trip.
    atomicOr(&g_bits[a][b >> 5], 1u << (b & 31));
    const int rank = atomicAdd(&g_cnt[a][b], 1);
    if (rank < CAP) {
        g_slot[a][b][rank] = v;
    } else {
        const int o = atomicAdd(&g_ovf_cnt[a], 1);
        g_ovf[a][o] = v;
    }
}

// ---------------------------------------------------------------------------
// Kernel 2: search. Speculative parallel scan of buckets b-1, b, b+1; the
// bitmask walk runs only for the ~6%/side of lanes whose coverage flags say
// the pred/succ might be farther. Exactness:
//   values <= v live only in buckets <= b; values > v only in buckets >= b.
//   low side exact if own bucket has a value <= v, or b-1 is non-empty;
//   otherwise pred is in the nearest non-empty bucket < b-1 (sbits walk).
//   (symmetric for the high side)
// ---------------------------------------------------------------------------
__global__ void __launch_bounds__(NTHR, 1)
search_kernel(const float* __restrict__ x, const float* __restrict__ y,
              float* __restrict__ out) {
    __shared__ unsigned sbits[NBW];   // opposite array's non-empty bitmask (1KB)
    __shared__ float    ws[NTHR / 32];
    __shared__ float    fin[2];
    __shared__ int      last;

    const int tid = threadIdx.x;
    const int gid = blockIdx.x * NTHR + tid;     // 0..32767
    const int a   = (gid >= NELEM);              // uniform per block
    const int idx = a ? (gid - NELEM) : gid;
    const float v = a ? __ldg(&y[idx]) : __ldg(&x[idx]);
    const int  b  = bucket_of(v);
    const int  sa = 1 - a;

    // All independent loads issue together: ovf count, sbits stage, and the
    // three speculative bucket scans (each: cnt + 2x LDG.128).
    const int oc = g_ovf_cnt[sa];                // normally 0
    if (tid < NBW) sbits[tid] = g_bits[sa][tid];

    const int cl = (b > 0)      ? g_cnt[sa][b - 1] : 0;
    const int ch = (b < NB - 1) ? g_cnt[sa][b + 1] : 0;

    bool hasLow, hasHigh;
    float best = scan_bucket_flags(sa, b, v, 3.4e38f, &hasLow, &hasHigh);
    if (b > 0)      best = scan_bucket(sa, b - 1, v, best);
    if (b < NB - 1) best = scan_bucket(sa, b + 1, v, best);

    __syncthreads();                             // sbits ready (overlapped above)

    // Rare fallbacks: side not covered by b-1/b/b+1.
    if (b > 0 && !hasLow && cl == 0) {
        const int bl = prev_ne(sbits, b - 1);    // nearest non-empty < b-1
        if (bl >= 0) best = scan_bucket(sa, bl, v, best);
    }
    if (b < NB - 1 && !hasHigh && ch == 0) {
        const int br = next_ne(sbits, b + 1);    // nearest non-empty > b+1
        if (br >= 0) best = scan_bucket(sa, br, v, best);
    }

    for (int i = 0; i < oc; i++)                 // normally zero iterations
        best = fminf(best, fabsf(g_ovf[sa][i] - v));

    // deterministic block reduction (16 warps)
    float d = best;
#pragma unroll
    for (int o = 16; o; o >>= 1) d += __shfl_xor_sync(0xffffffffu, d, o);
    if ((tid & 31) == 0) ws[tid >> 5] = d;
    __syncthreads();
    if (tid == 0) {
        float sum = 0.f;
#pragma unroll
        for (int i = 0; i < NTHR / 32; i++) sum += ws[i];
        g_partials[blockIdx.x] = sum;
        __threadfence();
        last = (atomicAdd(&g_done, 1) == NBLK - 1);
    }
    __syncthreads();

    // Last-arriving block: fixed-tree final reduction (deterministic),
    // output write, then state reset for the next graph replay.
    if (last) {
        if (tid < NBLK) {                         // 64 partials, 2 warps
            float p = g_partials[tid];
#pragma unroll
            for (int o = 16; o; o >>= 1) p += __shfl_xor_sync(0xffffffffu, p, o);
            if ((tid & 31) == 0) fin[tid >> 5] = p;
        }
        __syncthreads();
        if (tid == 0) {
            out[0] = 0.5f * (fin[0] + fin[1]) * (1.0f / 16384.0f);  // ALPHA=0.5
            g_ovf_cnt[0] = 0; g_ovf_cnt[1] = 0;
            g_done = 0;
        }
        // reset (8 int4 iterations at 512 threads)
        int4* cz = reinterpret_cast<int4*>(g_cnt);
        for (int i = tid; i < (2 * NB) / 4; i += NTHR) cz[i] = make_int4(0, 0, 0, 0);
        int4* bz = reinterpret_cast<int4*>(g_bits);
        for (int i = tid; i < (2 * NBW) / 4; i += NTHR) bz[i] = make_int4(0, 0, 0, 0);
    }
}

// ---------------------------------------------------------------------------
extern "C" void kernel_launch(void* const* d_in, const int* in_sizes, int n_in,
                              void* d_out, int out_size) {
    const float* x = (const float*)d_in[0];
    const float* y = (const float*)d_in[1];
    float* out = (float*)d_out;
    build_kernel<<<NBLK, NTHR>>>(x, y);
    search_kernel<<<NBLK, NTHR>>>(x, y, out);
}

// round 17
// speedup vs baseline: 1.1233x; 1.1233x over previous
#include <cuda_runtime.h>

#define NELEM 16384
#define NB 8192                       // buckets per array (power of two)
#define NBW (NB / 32)                 // bitmask words per array (256)
#define CAP 16                        // slots per bucket (lambda=2 -> P(>16) ~ 1e-10)
// build shape: 16 warps/SM hides the atomic round-trips (R16 measurement)
#define BNBLK 64
#define BNTHR 512
// search shape: R15 measurement (10.1us)
#define SNBLK 128
#define SNTHR 256
#define RANGE_LO (-6.0f)
#define RANGE_HI (6.0f)
#define INV_BW ((float)NB / (RANGE_HI - RANGE_LO))

// Scratch (device globals; no allocations). Zero-initialized at load; the
// search kernel's last-done block re-zeroes all mutable state, and the next
// graph replay's build kernel starts only after the search kernel completes,
// so every replay sees identical initial state.
// Slots beyond a bucket's final count are NEVER written in any replay (same
// input -> same counts), so unconditional slot reads see zero-init data that
// the idx<cnt mask discards.
__device__ int      g_cnt[2][NB];        // per-bucket counts (atomic rank source)
__device__ unsigned g_bits[2][NBW];      // non-empty bucket bitmask
__device__ float    g_slot[2][NB][CAP];  // bucket slots (64B-aligned per bucket)
__device__ int      g_ovf_cnt[2];        // overflow counts (normally 0)
__device__ float    g_ovf[2][NELEM];     // overflow values (worst-case capacity)
__device__ float    g_partials[SNBLK];
__device__ int      g_done;              // completion counter (search kernel)

__device__ __forceinline__ int bucket_of(float v) {
    int b = (int)((v - RANGE_LO) * INV_BW);
    return min(max(b, 0), NB - 1);       // clamp outliers into end buckets
}

// Vectorized bucket scan. Slots 0..7 unconditional (2x LDG.128, parallel with
// the cnt load); slots 8..15 only for the ~0.02% of buckets with c>8.
__device__ __forceinline__ float scan_bucket(int sa, int bkt, float v, float best) {
    const int c = min(g_cnt[sa][bkt], CAP);
    const float4* sv = reinterpret_cast<const float4*>(g_slot[sa][bkt]);
#pragma unroll
    for (int k = 0; k < 2; k++) {
        const float4 s = sv[k];
        const int i0 = k * 4;
        if (i0 + 0 < c) best = fminf(best, fabsf(s.x - v));
        if (i0 + 1 < c) best = fminf(best, fabsf(s.y - v));
        if (i0 + 2 < c) best = fminf(best, fabsf(s.z - v));
        if (i0 + 3 < c) best = fminf(best, fabsf(s.w - v));
    }
    if (c > 8) {
#pragma unroll
        for (int k = 2; k < 4; k++) {
            const float4 s = sv[k];
            const int i0 = k * 4;
            if (i0 + 0 < c) best = fminf(best, fabsf(s.x - v));
            if (i0 + 1 < c) best = fminf(best, fabsf(s.y - v));
            if (i0 + 2 < c) best = fminf(best, fabsf(s.z - v));
            if (i0 + 3 < c) best = fminf(best, fabsf(s.w - v));
        }
    }
    return best;
}

// highest set bit index < b, or -1 (smem bitmask)
__device__ __forceinline__ int prev_ne(const unsigned* bits, int b) {
    int w = b >> 5;
    unsigned m = bits[w] & ((1u << (b & 31)) - 1u);
    while (true) {
        if (m) return (w << 5) + 31 - __clz(m);
        if (--w < 0) return -1;
        m = bits[w];
    }
}
// lowest set bit index > b, or -1 (smem bitmask)
__device__ __forceinline__ int next_ne(const unsigned* bits, int b) {
    int w = b >> 5;
    const int r = b & 31;
    unsigned m = bits[w] & ((r == 31) ? 0u : (0xFFFFFFFFu << (r + 1)));
    while (true) {
        if (m) return (w << 5) + __ffs(m) - 1;
        if (++w >= NBW) return -1;
        m = bits[w];
    }
}

// ---------------------------------------------------------------------------
// Kernel 1: build — fused histogram + scatter + bitmask. 64x512: 16 warps/SM
// to hide the atomic round-trips. Graph edge to search = synchronization.
// ---------------------------------------------------------------------------
__global__ void __launch_bounds__(BNTHR, 1)
build_kernel(const float* __restrict__ x, const float* __restrict__ y) {
    const int gid = blockIdx.x * BNTHR + threadIdx.x;  // 0..32767
    const int a   = (gid >= NELEM);
    const int idx = a ? (gid - NELEM) : gid;
    const float v = a ? __ldg(&y[idx]) : __ldg(&x[idx]);
    const int  b  = bucket_of(v);

    // atomicOr first (no return needed): overlaps the atomicAdd round-trip.
    atomicOr(&g_bits[a][b >> 5], 1u << (b & 31));
    const int rank = atomicAdd(&g_cnt[a][b], 1);
    if (rank < CAP) {
        g_slot[a][b][rank] = v;
    } else {
        const int o = atomicAdd(&g_ovf_cnt[a], 1);
        g_ovf[a][o] = v;
    }
}

// ---------------------------------------------------------------------------
// Kernel 2: search — exact <=3-bucket NN per query (own bucket + nearest
// non-empty below/above found via smem-staged bitmask) + deterministic
// reduce; finalize via done-counter; reset state for the next replay.
// ---------------------------------------------------------------------------
__global__ void __launch_bounds__(SNTHR, 1)
search_kernel(const float* __restrict__ x, const float* __restrict__ y,
              float* __restrict__ out) {
    __shared__ unsigned sbits[NBW];   // opposite array's non-empty bitmask (1KB)
    __shared__ float    ws[SNTHR / 32];
    __shared__ float    fin[4];
    __shared__ int      last;

    const int tid = threadIdx.x;
    const int gid = blockIdx.x * SNTHR + tid;    // 0..32767
    const int a   = (gid >= NELEM);              // uniform per block
    const int idx = a ? (gid - NELEM) : gid;
    const float v = a ? __ldg(&y[idx]) : __ldg(&x[idx]);
    const int  b  = bucket_of(v);
    const int  sa = 1 - a;

    const int oc = g_ovf_cnt[sa];                // issue early; normally 0
    // Stage opposite bitmask to smem (one coalesced word per thread).
    sbits[tid] = g_bits[sa][tid];
    // Own-bucket scan issues before the staging sync (doesn't need sbits).
    float best = scan_bucket(sa, b, v, 3.4e38f);
    __syncthreads();

    const int bl = prev_ne(sbits, b);
    const int br = next_ne(sbits, b);
    if (bl >= 0) best = scan_bucket(sa, bl, v, best);
    if (br >= 0) best = scan_bucket(sa, br, v, best);

    for (int i = 0; i < oc; i++)                 // normally zero iterations
        best = fminf(best, fabsf(g_ovf[sa][i] - v));

    // deterministic block reduction
    float d = best;
#pragma unroll
    for (int o = 16; o; o >>= 1) d += __shfl_xor_sync(0xffffffffu, d, o);
    if ((tid & 31) == 0) ws[tid >> 5] = d;
    __syncthreads();
    if (tid == 0) {
        float sum = 0.f;
#pragma unroll
        for (int i = 0; i < SNTHR / 32; i++) sum += ws[i];
        g_partials[blockIdx.x] = sum;
        __threadfence();
        last = (atomicAdd(&g_done, 1) == SNBLK - 1);
    }
    __syncthreads();

    // Last-arriving block: fixed-tree final reduction (deterministic),
    // output write, then state reset for the next graph replay.
    if (last) {
        if (tid < SNBLK) {                        // 128 partials, 4 warps
            float p = g_partials[tid];
#pragma unroll
            for (int o = 16; o; o >>= 1) p += __shfl_xor_sync(0xffffffffu, p, o);
            if ((tid & 31) == 0) fin[tid >> 5] = p;
        }
        __syncthreads();
        if (tid == 0) {
            out[0] = 0.5f * (fin[0] + fin[1] + fin[2] + fin[3]) * (1.0f / 16384.0f);
            g_ovf_cnt[0] = 0; g_ovf_cnt[1] = 0;
            g_done = 0;
        }
        // reset state (parallel int4 stores)
        int4* cz = reinterpret_cast<int4*>(g_cnt);
        for (int i = tid; i < (2 * NB) / 4; i += SNTHR) cz[i] = make_int4(0, 0, 0, 0);
        int4* bz = reinterpret_cast<int4*>(g_bits);
        for (int i = tid; i < (2 * NBW) / 4; i += SNTHR) bz[i] = make_int4(0, 0, 0, 0);
    }
}

// ---------------------------------------------------------------------------
extern "C" void kernel_launch(void* const* d_in, const int* in_sizes, int n_in,
                              void* d_out, int out_size) {
    const float* x = (const float*)d_in[0];
    const float* y = (const float*)d_in[1];
    float* out = (float*)d_out;
    build_kernel<<<BNBLK, BNTHR>>>(x, y);
    search_kernel<<<SNBLK, SNTHR>>>(x, y, out);
}